// round 13
// baseline (speedup 1.0000x reference)
#include <cuda_runtime.h>
#include <cstdint>

#define B_   2
#define C_   64
#define H_   192
#define W_   192
#define HW_  (H_*W_)
#define NP_  (B_*HW_)
#define O_   64
#define K_   9
#define J_   576
#define EPS_ 1e-5f
#define PXB  128                   // pixels per k_main block
#define NBLK (HW_/PXB)             // k_main blocks per batch image (288)

// ---------------- scratch (no allocations allowed) ----------------
__device__ float    g_xnhwc[B_*HW_*C_];  // x transposed to [B][H][W][C]
__device__ float    g_off[27*NP_];       // planar: [slot][pixel]
__device__ uint32_t g_wt_hi[J_*O_];      // dcn_w transposed [j][o], tf32 hi
__device__ uint32_t g_wt_lo[J_*O_];      // tf32(lo residual)
__device__ float2   g_psum[B_*O_*NBLK];  // per-(b,o,block) partial (sum, sumsq)

// tf32 conversion: destination must be a .b32 register
__device__ __forceinline__ uint32_t tf32_hi(float v) {
    uint32_t r;
    asm("cvt.rna.tf32.f32 %0, %1;" : "=r"(r) : "f"(v));
    return r;
}
__device__ __forceinline__ void mma_tf32(float* c, const uint32_t* a, uint32_t b0, uint32_t b1) {
    asm volatile(
        "mma.sync.aligned.m16n8k8.row.col.f32.tf32.tf32.f32 "
        "{%0,%1,%2,%3}, {%4,%5,%6,%7}, {%8,%9}, {%0,%1,%2,%3};"
        : "+f"(c[0]), "+f"(c[1]), "+f"(c[2]), "+f"(c[3])
        : "r"(a[0]), "r"(a[1]), "r"(a[2]), "r"(a[3]),
          "r"(b0),  "r"(b1));
}

// ---------------- kernel 0: NCHW -> NHWC transpose ----------------
__global__ void k_transpose(const float* __restrict__ x) {
    __shared__ float t[32][33];
    int xt = blockIdx.x % (W_/32);
    int ct = blockIdx.x / (W_/32);
    int y  = blockIdx.y, b = blockIdx.z;
    int tx = threadIdx.x, ty = threadIdx.y;
#pragma unroll
    for (int i = 0; i < 4; i++) {
        int c  = ct*32 + ty + i*8;
        int xx = xt*32 + tx;
        t[ty + i*8][tx] = x[((b*C_ + c)*H_ + y)*W_ + xx];
    }
    __syncthreads();
#pragma unroll
    for (int i = 0; i < 4; i++) {
        int xx = xt*32 + ty + i*8;
        int c  = ct*32 + tx;
        g_xnhwc[(((b*H_ + y)*W_ + xx) << 6) + c] = t[tx][ty + i*8];
    }
}

// ------ kernel 1: dcn_w -> [j][o], pre-split into tf32 hi/lo ------
__global__ void k_wprep(const float* __restrict__ dcn_w) {
    int t = blockIdx.x*256 + threadIdx.x;     // t = j*64 + o
    if (t < J_*O_) {
        int o = t & 63;
        int j = t >> 6;
        int c = j & 63;
        int k = j >> 6;
        float v = dcn_w[o*J_ + c*K_ + k];
        uint32_t hi = tf32_hi(v);
        g_wt_hi[t] = hi;
        g_wt_lo[t] = tf32_hi(v - __uint_as_float(hi));
    }
}

// ------- kernel 2: dwconv + BN + ReLU + 1x1 -> offsets / mask -------
__global__ void __launch_bounds__(256) k_offsets(
    const float* __restrict__ dw_w, const float* __restrict__ dw_b,
    const float* __restrict__ bn_g, const float* __restrict__ bn_b,
    const float* __restrict__ bn_m, const float* __restrict__ bn_v,
    const float* __restrict__ pw_w, const float* __restrict__ pw_b)
{
    __shared__ float xt[3*34*64];
    __shared__ float hs[32*64];
    __shared__ float4 ws[16*27];
    __shared__ float pb[27];

    int tid = threadIdx.x;
    int gp0 = blockIdx.x * 32;
    int b   = gp0 / HW_;
    int rem = gp0 % HW_;
    int y   = rem / W_;
    int x0  = rem % W_;

    for (int e4 = tid; e4 < 3*34*16; e4 += 256) {
        int c4 = e4 & 15;
        int t2 = e4 >> 4;
        int xi = t2 % 34;
        int r  = t2 / 34;
        int yy = y - 1 + r;
        int xx = x0 - 1 + xi;
        float4 v = make_float4(0.f, 0.f, 0.f, 0.f);
        if ((unsigned)yy < H_ && (unsigned)xx < W_)
            v = *(const float4*)(g_xnhwc + (((b*H_ + yy)*W_ + xx) << 6) + c4*4);
        ((float4*)xt)[e4] = v;
    }
    for (int e = tid; e < 16*27; e += 256) {
        int o  = e % 27;
        int i4 = e / 27;
        const float* src = pw_w + o*64 + i4*4;
        ws[e] = make_float4(src[0], src[1], src[2], src[3]);
    }
    if (tid < 27) pb[tid] = pw_b[tid];
    __syncthreads();

#pragma unroll
    for (int i = 0; i < 8; i++) {
        int e = tid + i*256;
        int c = e & 63;
        int p = e >> 6;
        float acc = 0.f;
#pragma unroll
        for (int ky = 0; ky < 3; ky++) {
#pragma unroll
            for (int kx = 0; kx < 3; kx++) {
                acc += dw_w[c*9 + ky*3 + kx] * xt[(ky*34 + (p + kx))*64 + c];
            }
        }
        float s = bn_g[c] * rsqrtf(bn_v[c] + EPS_);
        hs[e] = fmaxf((acc + dw_b[c] - bn_m[c]) * s + bn_b[c], 0.f);
    }
    __syncthreads();

    for (int e = tid; e < 32*27; e += 256) {
        int p = e / 27;
        int o = e - p*27;
        float om = pb[o];
        const float4* hv = (const float4*)(hs + p*64);
#pragma unroll
        for (int i4 = 0; i4 < 16; i4++) {
            float4 h4 = hv[i4];
            float4 w4 = ws[i4*27 + o];
            om += h4.x*w4.x + h4.y*w4.y + h4.z*w4.z + h4.w*w4.w;
        }
        int slot;
        float v;
        if (o < 18) { slot = (o & 1)*9 + (o >> 1); v = om; }
        else        { slot = o; v = 1.f / (1.f + expf(-om)); }
        g_off[slot*NP_ + gp0 + p] = v;
    }
}

// ------- kernel 3: deformable gather + tf32 mma projection -------
// 128 px x 64 o per block, 9 taps of K=64; 3xTF32 split; W pre-split in gmem.
#define AST 68                                   // val_s row stride
#define WST 72                                   // w tile row stride
#define SMEM_FLOATS (PXB*AST + 2*64*WST)
#define SMEM_BYTES  (SMEM_FLOATS*4)

__global__ void __launch_bounds__(256, 3) k_main(float* __restrict__ out) {
    extern __shared__ __align__(16) float sm[];
    float*    val_s = sm;                                  // [p][c], stride AST
    uint32_t* wh_s  = (uint32_t*)(sm + PXB*AST);           // [c][o] hi
    uint32_t* wl_s  = (uint32_t*)(sm + PXB*AST + 64*WST);  // [c][o] lo

    int tid  = threadIdx.x;
    int lane = tid & 31;
    int warp = tid >> 5;
    int g    = lane >> 2;                        // fragment group 0..7
    int t    = lane & 3;                         // thread-in-group 0..3
    int gp0  = blockIdx.x * PXB;
    int b    = gp0 / HW_;
    int rem0 = gp0 % HW_;

    int c4 = tid & 15;                           // gather: channel quad
    int pi = tid >> 4;                           // gather: pixel sub-index

    float acc[8][4];
#pragma unroll
    for (int ni = 0; ni < 8; ni++)
#pragma unroll
        for (int r = 0; r < 4; r++) acc[ni][r] = 0.f;

#pragma unroll 1
    for (int k = 0; k < 9; k++) {
        if (k) __syncthreads();                  // prev GEMM done with smem

        // ---- load W hi/lo chunks [64][64] (stride 72) ----
        for (int e = tid; e < 64*16; e += 256) {
            int row  = e >> 4;
            int quad = e & 15;
            *(uint4*)(wh_s + row*WST + quad*4) =
                *(const uint4*)(g_wt_hi + k*4096 + row*64 + quad*4);
            *(uint4*)(wl_s + row*WST + quad*4) =
                *(const uint4*)(g_wt_lo + k*4096 + row*64 + quad*4);
        }

        // ---- gather this tap: 16 lanes per pixel (one float4 each) ----
        int ky = k/3 - 1, kx = k%3 - 1;
#pragma unroll 1
        for (int it = 0; it < PXB/16; it++) {
            int p   = it*16 + pi;
            int gp  = gp0 + p;
            int rem = rem0 + p;
            int y0  = rem / W_;
            int x0  = rem - y0*W_;

            float dy = g_off[k*NP_ + gp];
            float dx = g_off[(9+k)*NP_ + gp];
            float m  = g_off[(18+k)*NP_ + gp];
            float py = (float)(y0 + ky) + dy;
            float px = (float)(x0 + kx) + dx;
            float fy0 = floorf(py), fx0 = floorf(px);
            float wy1 = py - fy0,   wx1 = px - fx0;
            float wy0 = 1.f - wy1,  wx0 = 1.f - wx1;
            int   iy  = (int)fy0,   ix  = (int)fx0;

            float wts[4] = { wy0*wx0*m, wy0*wx1*m, wy1*wx0*m, wy1*wx1*m };
            int   ys[4]  = { iy, iy, iy+1, iy+1 };
            int   xs[4]  = { ix, ix+1, ix, ix+1 };

            float ax = 0.f, ay = 0.f, az = 0.f, aw = 0.f;
#pragma unroll
            for (int cn = 0; cn < 4; cn++) {
                bool v = (unsigned)ys[cn] < H_ && (unsigned)xs[cn] < W_;
                float wv = v ? wts[cn] : 0.f;
                const float* bp = v ? g_xnhwc + (((b*H_ + ys[cn])*W_ + xs[cn]) << 6)
                                    : g_xnhwc;
                float4 c = *(const float4*)(bp + c4*4);
                ax += wv*c.x; ay += wv*c.y; az += wv*c.z; aw += wv*c.w;
            }
            *(float4*)(val_s + p*AST + c4*4) = make_float4(ax, ay, az, aw);
        }
        __syncthreads();

        // ---- GEMM chunk via mma.sync tf32 (3-pass split), m16 tile ----
#pragma unroll
        for (int kq = 0; kq < 8; kq++) {
            int c0 = kq*8;
            int r0 = warp*16 + g;
            uint32_t ahi[4], alo[4];
            {
                float v0 = val_s[r0*AST     + c0 + t];
                float v1 = val_s[(r0+8)*AST + c0 + t];
                float v2 = val_s[r0*AST     + c0 + t + 4];
                float v3 = val_s[(r0+8)*AST + c0 + t + 4];
                ahi[0] = tf32_hi(v0); alo[0] = tf32_hi(v0 - __uint_as_float(ahi[0]));
                ahi[1] = tf32_hi(v1); alo[1] = tf32_hi(v1 - __uint_as_float(ahi[1]));
                ahi[2] = tf32_hi(v2); alo[2] = tf32_hi(v2 - __uint_as_float(ahi[2]));
                ahi[3] = tf32_hi(v3); alo[3] = tf32_hi(v3 - __uint_as_float(ahi[3]));
            }
#pragma unroll
            for (int ni = 0; ni < 8; ni++) {
                uint32_t bh0 = wh_s[(c0+t)*WST   + ni*8 + g];
                uint32_t bh1 = wh_s[(c0+t+4)*WST + ni*8 + g];
                uint32_t bl0 = wl_s[(c0+t)*WST   + ni*8 + g];
                uint32_t bl1 = wl_s[(c0+t+4)*WST + ni*8 + g];
                mma_tf32(acc[ni], ahi, bh0, bh1);
                mma_tf32(acc[ni], ahi, bl0, bl1);
                mma_tf32(acc[ni], alo, bh0, bh1);
            }
        }
    }

    // ---- epilogue: stage [o][p] (stride 132), psum + coalesced store ----
    __syncthreads();
    float* stg = val_s;                          // 64*132 = 8448 <= 128*68
#pragma unroll
    for (int ni = 0; ni < 8; ni++) {
        int o = ni*8 + 2*t;
        int r = warp*16 + g;
        stg[o*132 + r]         = acc[ni][0];
        stg[(o+1)*132 + r]     = acc[ni][1];
        stg[o*132 + r + 8]     = acc[ni][2];
        stg[(o+1)*132 + r + 8] = acc[ni][3];
    }
    __syncthreads();

    // per-(block,o) partial sums for instance norm (deterministic, no atomics)
    {
        int o = tid >> 2;
        int q = tid & 3;
        const float* base = stg + o*132 + q*32;
        float s = 0.f, ss = 0.f;
#pragma unroll
        for (int i = 0; i < 32; i++) { float v = base[i]; s += v; ss += v*v; }
        s  += __shfl_xor_sync(~0u, s, 1);  ss += __shfl_xor_sync(~0u, ss, 1);
        s  += __shfl_xor_sync(~0u, s, 2);  ss += __shfl_xor_sync(~0u, ss, 2);
        if (q == 0) {
            int blk = rem0 / PXB;
            g_psum[(b*O_ + o)*NBLK + blk] = make_float2(s, ss);
        }
    }

#pragma unroll
    for (int r = 0; r < 32; r++) {
        int q = r*256 + tid;
        int o = q >> 7;
        int p = q & 127;
        out[(b*O_ + o)*HW_ + rem0 + p] = stg[o*132 + p];
    }
}

// ------- kernel 4: reduce partials, then normalize + ReLU in-place -------
__global__ void __launch_bounds__(256) k_inorm(float* __restrict__ out) {
    int bo = blockIdx.x;
    float s = 0.f, ss = 0.f;
    for (int i = threadIdx.x; i < NBLK; i += 256) {
        float2 v = g_psum[bo*NBLK + i];
        s += v.x; ss += v.y;
    }
#pragma unroll
    for (int off = 16; off; off >>= 1) {
        s  += __shfl_xor_sync(~0u, s,  off);
        ss += __shfl_xor_sync(~0u, ss, off);
    }
    __shared__ float rs[8], rss[8];
    __shared__ float mu_s, rstd_s;
    if ((threadIdx.x & 31) == 0) { rs[threadIdx.x>>5] = s; rss[threadIdx.x>>5] = ss; }
    __syncthreads();
    if (threadIdx.x == 0) {
        float S = 0.f, SS = 0.f;
#pragma unroll
        for (int i = 0; i < 8; i++) { S += rs[i]; SS += rss[i]; }
        float mu  = S / (float)HW_;
        float var = SS / (float)HW_ - mu*mu;
        mu_s = mu;
        rstd_s = rsqrtf(var + EPS_);
    }
    __syncthreads();
    float mu = mu_s, rstd = rstd_s;
    float4* row = (float4*)(out + bo*HW_);
    for (int i = threadIdx.x; i < HW_/4; i += 256) {
        float4 v = row[i];
        v.x = fmaxf((v.x - mu)*rstd, 0.f);
        v.y = fmaxf((v.y - mu)*rstd, 0.f);
        v.z = fmaxf((v.z - mu)*rstd, 0.f);
        v.w = fmaxf((v.w - mu)*rstd, 0.f);
        row[i] = v;
    }
}

// ---------------- launch ----------------
extern "C" void kernel_launch(void* const* d_in, const int* in_sizes, int n_in,
                              void* d_out, int out_size) {
    (void)in_sizes; (void)n_in; (void)out_size;
    const float* x     = (const float*)d_in[0];
    const float* dw_w  = (const float*)d_in[1];
    const float* dw_b  = (const float*)d_in[2];
    const float* bn_g  = (const float*)d_in[3];
    const float* bn_b  = (const float*)d_in[4];
    const float* bn_m  = (const float*)d_in[5];
    const float* bn_v  = (const float*)d_in[6];
    const float* pw_w  = (const float*)d_in[7];
    const float* pw_b  = (const float*)d_in[8];
    const float* dcn_w = (const float*)d_in[9];
    // d_in[10] = dcn_b: exactly cancelled by the instance norm -> unused.
    float* out = (float*)d_out;

    cudaFuncSetAttribute(k_main, cudaFuncAttributeMaxDynamicSharedMemorySize, SMEM_BYTES);

    k_transpose<<<dim3((W_/32)*(C_/32), H_, B_), dim3(32, 8)>>>(x);
    k_wprep<<<(J_*O_ + 255)/256, 256>>>(dcn_w);
    k_offsets<<<(B_*HW_)/32, 256>>>(dw_w, dw_b, bn_g, bn_b, bn_m, bn_v, pw_w, pw_b);
    k_main<<<NP_/PXB, 256, SMEM_BYTES>>>(out);
    k_inorm<<<B_*O_, 256>>>(out);
}

// round 14
// speedup vs baseline: 1.0529x; 1.0529x over previous
#include <cuda_runtime.h>
#include <cstdint>

#define B_   2
#define C_   64
#define H_   192
#define W_   192
#define HW_  (H_*W_)
#define NP_  (B_*HW_)
#define O_   64
#define K_   9
#define J_   576
#define EPS_ 1e-5f
#define PXB  256                   // pixels per k_main block
#define NBLK (HW_/PXB)             // k_main blocks per batch image (144)

// ---------------- scratch (no allocations allowed) ----------------
__device__ float    g_xnhwc[B_*HW_*C_];  // x transposed to [B][H][W][C]
__device__ float    g_off[27*NP_];       // planar: [slot][pixel]
__device__ uint32_t g_wt_hi[J_*O_];      // dcn_w transposed [j][o], tf32 hi
__device__ uint32_t g_wt_lo[J_*O_];      // tf32(lo residual)
__device__ float2   g_psum[B_*O_*NBLK];  // per-(b,o,block) partial (sum, sumsq)

// tf32 conversion: destination must be a .b32 register
__device__ __forceinline__ uint32_t tf32_hi(float v) {
    uint32_t r;
    asm("cvt.rna.tf32.f32 %0, %1;" : "=r"(r) : "f"(v));
    return r;
}
__device__ __forceinline__ void mma_tf32(float* c, const uint32_t* a, uint32_t b0, uint32_t b1) {
    asm volatile(
        "mma.sync.aligned.m16n8k8.row.col.f32.tf32.tf32.f32 "
        "{%0,%1,%2,%3}, {%4,%5,%6,%7}, {%8,%9}, {%0,%1,%2,%3};"
        : "+f"(c[0]), "+f"(c[1]), "+f"(c[2]), "+f"(c[3])
        : "r"(a[0]), "r"(a[1]), "r"(a[2]), "r"(a[3]),
          "r"(b0),  "r"(b1));
}

// ---------------- kernel 0: NCHW -> NHWC transpose ----------------
__global__ void k_transpose(const float* __restrict__ x) {
    __shared__ float t[32][33];
    int xt = blockIdx.x % (W_/32);
    int ct = blockIdx.x / (W_/32);
    int y  = blockIdx.y, b = blockIdx.z;
    int tx = threadIdx.x, ty = threadIdx.y;
#pragma unroll
    for (int i = 0; i < 4; i++) {
        int c  = ct*32 + ty + i*8;
        int xx = xt*32 + tx;
        t[ty + i*8][tx] = x[((b*C_ + c)*H_ + y)*W_ + xx];
    }
    __syncthreads();
#pragma unroll
    for (int i = 0; i < 4; i++) {
        int xx = xt*32 + ty + i*8;
        int c  = ct*32 + tx;
        g_xnhwc[(((b*H_ + y)*W_ + xx) << 6) + c] = t[tx][ty + i*8];
    }
}

// ------ kernel 1: dcn_w -> [j][o], pre-split into tf32 hi/lo ------
__global__ void k_wprep(const float* __restrict__ dcn_w) {
    int t = blockIdx.x*256 + threadIdx.x;     // t = j*64 + o
    if (t < J_*O_) {
        int o = t & 63;
        int j = t >> 6;
        int c = j & 63;
        int k = j >> 6;
        float v = dcn_w[o*J_ + c*K_ + k];
        uint32_t hi = tf32_hi(v);
        g_wt_hi[t] = hi;
        g_wt_lo[t] = tf32_hi(v - __uint_as_float(hi));
    }
}

// ------- kernel 2: dwconv + BN + ReLU + 1x1 -> offsets / mask -------
__global__ void __launch_bounds__(256) k_offsets(
    const float* __restrict__ dw_w, const float* __restrict__ dw_b,
    const float* __restrict__ bn_g, const float* __restrict__ bn_b,
    const float* __restrict__ bn_m, const float* __restrict__ bn_v,
    const float* __restrict__ pw_w, const float* __restrict__ pw_b)
{
    __shared__ float xt[3*34*64];
    __shared__ float hs[32*64];
    __shared__ float4 ws[16*27];
    __shared__ float pb[27];

    int tid = threadIdx.x;
    int gp0 = blockIdx.x * 32;
    int b   = gp0 / HW_;
    int rem = gp0 % HW_;
    int y   = rem / W_;
    int x0  = rem % W_;

    for (int e4 = tid; e4 < 3*34*16; e4 += 256) {
        int c4 = e4 & 15;
        int t2 = e4 >> 4;
        int xi = t2 % 34;
        int r  = t2 / 34;
        int yy = y - 1 + r;
        int xx = x0 - 1 + xi;
        float4 v = make_float4(0.f, 0.f, 0.f, 0.f);
        if ((unsigned)yy < H_ && (unsigned)xx < W_)
            v = *(const float4*)(g_xnhwc + (((b*H_ + yy)*W_ + xx) << 6) + c4*4);
        ((float4*)xt)[e4] = v;
    }
    for (int e = tid; e < 16*27; e += 256) {
        int o  = e % 27;
        int i4 = e / 27;
        const float* src = pw_w + o*64 + i4*4;
        ws[e] = make_float4(src[0], src[1], src[2], src[3]);
    }
    if (tid < 27) pb[tid] = pw_b[tid];
    __syncthreads();

#pragma unroll
    for (int i = 0; i < 8; i++) {
        int e = tid + i*256;
        int c = e & 63;
        int p = e >> 6;
        float acc = 0.f;
#pragma unroll
        for (int ky = 0; ky < 3; ky++) {
#pragma unroll
            for (int kx = 0; kx < 3; kx++) {
                acc += dw_w[c*9 + ky*3 + kx] * xt[(ky*34 + (p + kx))*64 + c];
            }
        }
        float s = bn_g[c] * rsqrtf(bn_v[c] + EPS_);
        hs[e] = fmaxf((acc + dw_b[c] - bn_m[c]) * s + bn_b[c], 0.f);
    }
    __syncthreads();

    for (int e = tid; e < 32*27; e += 256) {
        int p = e / 27;
        int o = e - p*27;
        float om = pb[o];
        const float4* hv = (const float4*)(hs + p*64);
#pragma unroll
        for (int i4 = 0; i4 < 16; i4++) {
            float4 h4 = hv[i4];
            float4 w4 = ws[i4*27 + o];
            om += h4.x*w4.x + h4.y*w4.y + h4.z*w4.z + h4.w*w4.w;
        }
        int slot;
        float v;
        if (o < 18) { slot = (o & 1)*9 + (o >> 1); v = om; }
        else        { slot = o; v = 1.f / (1.f + expf(-om)); }
        g_off[slot*NP_ + gp0 + p] = v;
    }
}

// ------- kernel 3: deformable gather + tf32 mma projection -------
// 256 px x 64 o per block, 9 taps of K=64. 3xTF32 split; W pre-split in gmem.
#define AST 68                                   // val_s row stride
#define WST 72                                   // w tile row stride
#define SMEM_FLOATS (PXB*AST + 2*64*WST)
#define SMEM_BYTES  (SMEM_FLOATS*4)

__global__ void __launch_bounds__(256, 2) k_main(float* __restrict__ out) {
    extern __shared__ __align__(16) float sm[];
    float*    val_s = sm;                                  // [p][c], stride AST
    uint32_t* wh_s  = (uint32_t*)(sm + PXB*AST);           // [c][o] hi
    uint32_t* wl_s  = (uint32_t*)(sm + PXB*AST + 64*WST);  // [c][o] lo

    int tid  = threadIdx.x;
    int lane = tid & 31;
    int warp = tid >> 5;
    int g    = lane >> 2;                        // fragment group 0..7
    int t    = lane & 3;                         // thread-in-group 0..3
    int gp0  = blockIdx.x * PXB;
    int b    = gp0 / HW_;
    int rem0 = gp0 % HW_;

    int c4 = tid & 15;                           // gather: channel quad
    int pi = tid >> 4;                           // gather: pixel sub-index

    float acc[2][8][4];
#pragma unroll
    for (int mi = 0; mi < 2; mi++)
#pragma unroll
        for (int ni = 0; ni < 8; ni++)
#pragma unroll
            for (int r = 0; r < 4; r++) acc[mi][ni][r] = 0.f;

#pragma unroll 1
    for (int k = 0; k < 9; k++) {
        if (k) __syncthreads();                  // prev GEMM done with smem

        // ---- load W hi/lo chunks [64][64] (stride 72) ----
        for (int e = tid; e < 64*16; e += 256) {
            int row  = e >> 4;
            int quad = e & 15;
            *(uint4*)(wh_s + row*WST + quad*4) =
                *(const uint4*)(g_wt_hi + k*4096 + row*64 + quad*4);
            *(uint4*)(wl_s + row*WST + quad*4) =
                *(const uint4*)(g_wt_lo + k*4096 + row*64 + quad*4);
        }

        // ---- gather this tap: 16 lanes per pixel (one float4 each) ----
        int ky = k/3 - 1, kx = k%3 - 1;
#pragma unroll 1
        for (int it = 0; it < PXB/16; it++) {
            int p   = it*16 + pi;
            int gp  = gp0 + p;
            int rem = rem0 + p;
            int y0  = rem / W_;
            int x0  = rem - y0*W_;

            float dy = g_off[k*NP_ + gp];
            float dx = g_off[(9+k)*NP_ + gp];
            float m  = g_off[(18+k)*NP_ + gp];
            float py = (float)(y0 + ky) + dy;
            float px = (float)(x0 + kx) + dx;
            float fy0 = floorf(py), fx0 = floorf(px);
            float wy1 = py - fy0,   wx1 = px - fx0;
            float wy0 = 1.f - wy1,  wx0 = 1.f - wx1;
            int   iy  = (int)fy0,   ix  = (int)fx0;

            float wts[4] = { wy0*wx0*m, wy0*wx1*m, wy1*wx0*m, wy1*wx1*m };
            int   ys[4]  = { iy, iy, iy+1, iy+1 };
            int   xs[4]  = { ix, ix+1, ix, ix+1 };

            float ax = 0.f, ay = 0.f, az = 0.f, aw = 0.f;
#pragma unroll
            for (int cn = 0; cn < 4; cn++) {
                bool v = (unsigned)ys[cn] < H_ && (unsigned)xs[cn] < W_;
                float wv = v ? wts[cn] : 0.f;
                const float* bp = v ? g_xnhwc + (((b*H_ + ys[cn])*W_ + xs[cn]) << 6)
                                    : g_xnhwc;
                float4 c = *(const float4*)(bp + c4*4);
                ax += wv*c.x; ay += wv*c.y; az += wv*c.z; aw += wv*c.w;
            }
            *(float4*)(val_s + p*AST + c4*4) = make_float4(ax, ay, az, aw);
        }
        __syncthreads();

        // ---- GEMM chunk via mma.sync tf32 (3-pass split) ----
#pragma unroll
        for (int kq = 0; kq < 8; kq++) {
            int c0 = kq*8;
            uint32_t ahi[2][4], alo[2][4];
#pragma unroll
            for (int mi = 0; mi < 2; mi++) {
                int r0 = warp*32 + mi*16 + g;
                float v0 = val_s[r0*AST       + c0 + t];
                float v1 = val_s[(r0+8)*AST   + c0 + t];
                float v2 = val_s[r0*AST       + c0 + t + 4];
                float v3 = val_s[(r0+8)*AST   + c0 + t + 4];
                ahi[mi][0] = tf32_hi(v0); alo[mi][0] = tf32_hi(v0 - __uint_as_float(ahi[mi][0]));
                ahi[mi][1] = tf32_hi(v1); alo[mi][1] = tf32_hi(v1 - __uint_as_float(ahi[mi][1]));
                ahi[mi][2] = tf32_hi(v2); alo[mi][2] = tf32_hi(v2 - __uint_as_float(ahi[mi][2]));
                ahi[mi][3] = tf32_hi(v3); alo[mi][3] = tf32_hi(v3 - __uint_as_float(ahi[mi][3]));
            }
#pragma unroll
            for (int ni = 0; ni < 8; ni++) {
                uint32_t bh0 = wh_s[(c0+t)*WST   + ni*8 + g];
                uint32_t bh1 = wh_s[(c0+t+4)*WST + ni*8 + g];
                uint32_t bl0 = wl_s[(c0+t)*WST   + ni*8 + g];
                uint32_t bl1 = wl_s[(c0+t+4)*WST + ni*8 + g];
                mma_tf32(acc[0][ni], ahi[0], bh0, bh1);
                mma_tf32(acc[1][ni], ahi[1], bh0, bh1);
                mma_tf32(acc[0][ni], ahi[0], bl0, bl1);
                mma_tf32(acc[1][ni], ahi[1], bl0, bl1);
                mma_tf32(acc[0][ni], alo[0], bh0, bh1);
                mma_tf32(acc[1][ni], alo[1], bh0, bh1);
            }
        }
    }

    // ---- epilogue: stage [o][p] (stride 260), psum + coalesced store ----
    __syncthreads();
    float* stg = val_s;                          // 64*260 = 16640 <= 256*68
#pragma unroll
    for (int mi = 0; mi < 2; mi++)
#pragma unroll
        for (int ni = 0; ni < 8; ni++) {
            int o = ni*8 + 2*t;
            int r = warp*32 + mi*16 + g;
            stg[o*260 + r]         = acc[mi][ni][0];
            stg[(o+1)*260 + r]     = acc[mi][ni][1];
            stg[o*260 + r + 8]     = acc[mi][ni][2];
            stg[(o+1)*260 + r + 8] = acc[mi][ni][3];
        }
    __syncthreads();

    // per-(block,o) partial sums for instance norm (deterministic, no atomics)
    {
        int o = tid >> 2;
        int q = tid & 3;
        const float* base = stg + o*260 + q*64;
        float s = 0.f, ss = 0.f;
#pragma unroll
        for (int i = 0; i < 64; i++) { float v = base[i]; s += v; ss += v*v; }
        s  += __shfl_xor_sync(~0u, s, 1);  ss += __shfl_xor_sync(~0u, ss, 1);
        s  += __shfl_xor_sync(~0u, s, 2);  ss += __shfl_xor_sync(~0u, ss, 2);
        if (q == 0) {
            int blk = rem0 / PXB;
            g_psum[(b*O_ + o)*NBLK + blk] = make_float2(s, ss);
        }
    }

#pragma unroll 1
    for (int o = 0; o < 64; o++)
        out[(b*O_ + o)*HW_ + rem0 + tid] = stg[o*260 + tid];
}

// ------- kernel 4: reduce partials, then normalize + ReLU in-place -------
__global__ void __launch_bounds__(256) k_inorm(float* __restrict__ out) {
    int bo = blockIdx.x;
    float s = 0.f, ss = 0.f;
    for (int i = threadIdx.x; i < NBLK; i += 256) {
        float2 v = g_psum[bo*NBLK + i];
        s += v.x; ss += v.y;
    }
#pragma unroll
    for (int off = 16; off; off >>= 1) {
        s  += __shfl_xor_sync(~0u, s,  off);
        ss += __shfl_xor_sync(~0u, ss, off);
    }
    __shared__ float rs[8], rss[8];
    __shared__ float mu_s, rstd_s;
    if ((threadIdx.x & 31) == 0) { rs[threadIdx.x>>5] = s; rss[threadIdx.x>>5] = ss; }
    __syncthreads();
    if (threadIdx.x == 0) {
        float S = 0.f, SS = 0.f;
#pragma unroll
        for (int i = 0; i < 8; i++) { S += rs[i]; SS += rss[i]; }
        float mu  = S / (float)HW_;
        float var = SS / (float)HW_ - mu*mu;
        mu_s = mu;
        rstd_s = rsqrtf(var + EPS_);
    }
    __syncthreads();
    float mu = mu_s, rstd = rstd_s;
    float4* row = (float4*)(out + bo*HW_);
    for (int i = threadIdx.x; i < HW_/4; i += 256) {
        float4 v = row[i];
        v.x = fmaxf((v.x - mu)*rstd, 0.f);
        v.y = fmaxf((v.y - mu)*rstd, 0.f);
        v.z = fmaxf((v.z - mu)*rstd, 0.f);
        v.w = fmaxf((v.w - mu)*rstd, 0.f);
        row[i] = v;
    }
}

// ---------------- launch ----------------
extern "C" void kernel_launch(void* const* d_in, const int* in_sizes, int n_in,
                              void* d_out, int out_size) {
    (void)in_sizes; (void)n_in; (void)out_size;
    const float* x     = (const float*)d_in[0];
    const float* dw_w  = (const float*)d_in[1];
    const float* dw_b  = (const float*)d_in[2];
    const float* bn_g  = (const float*)d_in[3];
    const float* bn_b  = (const float*)d_in[4];
    const float* bn_m  = (const float*)d_in[5];
    const float* bn_v  = (const float*)d_in[6];
    const float* pw_w  = (const float*)d_in[7];
    const float* pw_b  = (const float*)d_in[8];
    const float* dcn_w = (const float*)d_in[9];
    // d_in[10] = dcn_b: exactly cancelled by the instance norm -> unused.
    float* out = (float*)d_out;

    cudaFuncSetAttribute(k_main, cudaFuncAttributeMaxDynamicSharedMemorySize, SMEM_BYTES);

    k_transpose<<<dim3((W_/32)*(C_/32), H_, B_), dim3(32, 8)>>>(x);
    k_wprep<<<(J_*O_ + 255)/256, 256>>>(dcn_w);
    k_offsets<<<(B_*HW_)/32, 256>>>(dw_w, dw_b, bn_g, bn_b, bn_m, bn_v, pw_w, pw_b);
    k_main<<<NP_/PXB, 256, SMEM_BYTES>>>(out);
    k_inorm<<<B_*O_, 256>>>(out);
}

// round 15
// speedup vs baseline: 1.1712x; 1.1124x over previous
#include <cuda_runtime.h>
#include <cstdint>

#define B_   2
#define C_   64
#define H_   192
#define W_   192
#define HW_  (H_*W_)
#define NP_  (B_*HW_)
#define O_   64
#define K_   9
#define J_   576
#define EPS_ 1e-5f
#define PXB  256                   // pixels per k_main block
#define NBLK (HW_/PXB)             // k_main blocks per batch image (144)

// ---------------- scratch (no allocations allowed) ----------------
__device__ float    g_xnhwc[B_*HW_*C_];  // x transposed to [B][H][W][C]
__device__ float    g_off[27*NP_];       // planar: [slot][pixel]
__device__ uint32_t g_wb_hi[(J_/2)*O_];  // W bf16-hi pairs: [tap][cpair][o]
__device__ uint32_t g_wb_lo[(J_/2)*O_];  // W bf16-lo residual pairs
__device__ float2   g_psum[B_*O_*NBLK];  // per-(b,o,block) partial (sum, sumsq)

// pack (top16(a), top16(b)) -> bf16x2 {lo=a_hi16, hi=b_hi16} (RZ truncation)
__device__ __forceinline__ uint32_t pack_hi(float a, float b) {
    uint32_t d;
    asm("prmt.b32 %0, %1, %2, 0x7632;"
        : "=r"(d) : "r"(__float_as_uint(a)), "r"(__float_as_uint(b)));
    return d;
}
// pack residuals (a - bf16rz(a), b - bf16rz(b)) -> bf16x2 (RN)
__device__ __forceinline__ uint32_t pack_lo(float a, float b) {
    float la = a - __uint_as_float(__float_as_uint(a) & 0xffff0000u);
    float lb = b - __uint_as_float(__float_as_uint(b) & 0xffff0000u);
    uint32_t d;
    asm("cvt.rn.bf16x2.f32 %0, %1, %2;" : "=r"(d) : "f"(lb), "f"(la));
    return d;
}
__device__ __forceinline__ void mma_bf16(float* c, const uint32_t* a, uint32_t b0, uint32_t b1) {
    asm volatile(
        "mma.sync.aligned.m16n8k16.row.col.f32.bf16.bf16.f32 "
        "{%0,%1,%2,%3}, {%4,%5,%6,%7}, {%8,%9}, {%0,%1,%2,%3};"
        : "+f"(c[0]), "+f"(c[1]), "+f"(c[2]), "+f"(c[3])
        : "r"(a[0]), "r"(a[1]), "r"(a[2]), "r"(a[3]),
          "r"(b0),  "r"(b1));
}

// ---------------- kernel 0: NCHW -> NHWC transpose ----------------
__global__ void k_transpose(const float* __restrict__ x) {
    __shared__ float t[32][33];
    int xt = blockIdx.x % (W_/32);
    int ct = blockIdx.x / (W_/32);
    int y  = blockIdx.y, b = blockIdx.z;
    int tx = threadIdx.x, ty = threadIdx.y;
#pragma unroll
    for (int i = 0; i < 4; i++) {
        int c  = ct*32 + ty + i*8;
        int xx = xt*32 + tx;
        t[ty + i*8][tx] = x[((b*C_ + c)*H_ + y)*W_ + xx];
    }
    __syncthreads();
#pragma unroll
    for (int i = 0; i < 4; i++) {
        int xx = xt*32 + ty + i*8;
        int c  = ct*32 + tx;
        g_xnhwc[(((b*H_ + y)*W_ + xx) << 6) + c] = t[tx][ty + i*8];
    }
}

// ------ kernel 1: dcn_w -> per-tap channel-pair-packed bf16 hi/lo ------
__global__ void k_wprep(const float* __restrict__ dcn_w) {
    int t = blockIdx.x*256 + threadIdx.x;     // t = jp*64 + o
    if (t < (J_/2)*O_) {
        int o   = t & 63;
        int jp  = t >> 6;        // global pair index
        int tap = jp >> 5;
        int cp  = jp & 31;
        int c0  = cp*2;
        float v0 = dcn_w[o*J_ + c0*K_ + tap];
        float v1 = dcn_w[o*J_ + (c0+1)*K_ + tap];
        g_wb_hi[t] = pack_hi(v0, v1);
        g_wb_lo[t] = pack_lo(v0, v1);
    }
}

// ------- kernel 2: dwconv + BN + ReLU + 1x1 -> offsets / mask -------
__global__ void __launch_bounds__(256) k_offsets(
    const float* __restrict__ dw_w, const float* __restrict__ dw_b,
    const float* __restrict__ bn_g, const float* __restrict__ bn_b,
    const float* __restrict__ bn_m, const float* __restrict__ bn_v,
    const float* __restrict__ pw_w, const float* __restrict__ pw_b)
{
    __shared__ float xt[3*34*64];
    __shared__ float hs[32*64];
    __shared__ float4 ws[16*27];
    __shared__ float pb[27];

    int tid = threadIdx.x;
    int gp0 = blockIdx.x * 32;
    int b   = gp0 / HW_;
    int rem = gp0 % HW_;
    int y   = rem / W_;
    int x0  = rem % W_;

    for (int e4 = tid; e4 < 3*34*16; e4 += 256) {
        int c4 = e4 & 15;
        int t2 = e4 >> 4;
        int xi = t2 % 34;
        int r  = t2 / 34;
        int yy = y - 1 + r;
        int xx = x0 - 1 + xi;
        float4 v = make_float4(0.f, 0.f, 0.f, 0.f);
        if ((unsigned)yy < H_ && (unsigned)xx < W_)
            v = *(const float4*)(g_xnhwc + (((b*H_ + yy)*W_ + xx) << 6) + c4*4);
        ((float4*)xt)[e4] = v;
    }
    for (int e = tid; e < 16*27; e += 256) {
        int o  = e % 27;
        int i4 = e / 27;
        const float* src = pw_w + o*64 + i4*4;
        ws[e] = make_float4(src[0], src[1], src[2], src[3]);
    }
    if (tid < 27) pb[tid] = pw_b[tid];
    __syncthreads();

#pragma unroll
    for (int i = 0; i < 8; i++) {
        int e = tid + i*256;
        int c = e & 63;
        int p = e >> 6;
        float acc = 0.f;
#pragma unroll
        for (int ky = 0; ky < 3; ky++) {
#pragma unroll
            for (int kx = 0; kx < 3; kx++) {
                acc += dw_w[c*9 + ky*3 + kx] * xt[(ky*34 + (p + kx))*64 + c];
            }
        }
        float s = bn_g[c] * rsqrtf(bn_v[c] + EPS_);
        hs[e] = fmaxf((acc + dw_b[c] - bn_m[c]) * s + bn_b[c], 0.f);
    }
    __syncthreads();

    for (int e = tid; e < 32*27; e += 256) {
        int p = e / 27;
        int o = e - p*27;
        float om = pb[o];
        const float4* hv = (const float4*)(hs + p*64);
#pragma unroll
        for (int i4 = 0; i4 < 16; i4++) {
            float4 h4 = hv[i4];
            float4 w4 = ws[i4*27 + o];
            om += h4.x*w4.x + h4.y*w4.y + h4.z*w4.z + h4.w*w4.w;
        }
        int slot;
        float v;
        if (o < 18) { slot = (o & 1)*9 + (o >> 1); v = om; }
        else        { slot = o; v = 1.f / (1.f + expf(-om)); }
        g_off[slot*NP_ + gp0 + p] = v;
    }
}

// ------- kernel 3: deformable gather + bf16-split mma projection -------
// 256 px x 64 o per block, 9 taps of K=64; split-bf16 (hi/lo), m16n8k16.
#define AST 68                                   // val_s row stride (floats)
#define WPR 72                                   // W pair-row stride (uint32)
#define SMEM_FLOATS (PXB*AST + 2*32*WPR)
#define SMEM_BYTES  (SMEM_FLOATS*4)

__global__ void __launch_bounds__(256, 2) k_main(float* __restrict__ out) {
    extern __shared__ __align__(16) float sm[];
    float*    val_s = sm;                                  // [p][c], stride AST
    uint32_t* whb   = (uint32_t*)(sm + PXB*AST);           // [cpair][o] hi
    uint32_t* wlb   = whb + 32*WPR;                        // [cpair][o] lo

    int tid  = threadIdx.x;
    int lane = tid & 31;
    int warp = tid >> 5;
    int g    = lane >> 2;                        // fragment group 0..7
    int t    = lane & 3;                         // thread-in-group 0..3
    int gp0  = blockIdx.x * PXB;
    int b    = gp0 / HW_;
    int rem0 = gp0 % HW_;

    int c4 = tid & 15;                           // gather: channel quad
    int pi = tid >> 4;                           // gather: pixel sub-index

    float acc[2][8][4];
#pragma unroll
    for (int mi = 0; mi < 2; mi++)
#pragma unroll
        for (int ni = 0; ni < 8; ni++)
#pragma unroll
            for (int r = 0; r < 4; r++) acc[mi][ni][r] = 0.f;

#pragma unroll 1
    for (int k = 0; k < 9; k++) {
        if (k) __syncthreads();                  // prev GEMM done with smem

        // ---- load W hi/lo pair-chunks [32 pairs][64 o] (stride 72) ----
        for (int e = tid; e < 32*16; e += 256) {
            int row  = e >> 4;
            int quad = e & 15;
            *(uint4*)(whb + row*WPR + quad*4) =
                *(const uint4*)(g_wb_hi + k*2048 + row*64 + quad*4);
            *(uint4*)(wlb + row*WPR + quad*4) =
                *(const uint4*)(g_wb_lo + k*2048 + row*64 + quad*4);
        }

        // ---- gather this tap: 16 lanes per pixel (one float4 each) ----
        int ky = k/3 - 1, kx = k%3 - 1;
#pragma unroll 1
        for (int it = 0; it < PXB/16; it++) {
            int p   = it*16 + pi;
            int gp  = gp0 + p;
            int rem = rem0 + p;
            int y0  = rem / W_;
            int x0  = rem - y0*W_;

            float dy = g_off[k*NP_ + gp];
            float dx = g_off[(9+k)*NP_ + gp];
            float m  = g_off[(18+k)*NP_ + gp];
            float py = (float)(y0 + ky) + dy;
            float px = (float)(x0 + kx) + dx;
            float fy0 = floorf(py), fx0 = floorf(px);
            float wy1 = py - fy0,   wx1 = px - fx0;
            float wy0 = 1.f - wy1,  wx0 = 1.f - wx1;
            int   iy  = (int)fy0,   ix  = (int)fx0;

            float wts[4] = { wy0*wx0*m, wy0*wx1*m, wy1*wx0*m, wy1*wx1*m };
            int   ys[4]  = { iy, iy, iy+1, iy+1 };
            int   xs[4]  = { ix, ix+1, ix, ix+1 };

            float ax = 0.f, ay = 0.f, az = 0.f, aw = 0.f;
#pragma unroll
            for (int cn = 0; cn < 4; cn++) {
                bool v = (unsigned)ys[cn] < H_ && (unsigned)xs[cn] < W_;
                float wv = v ? wts[cn] : 0.f;
                const float* bp = v ? g_xnhwc + (((b*H_ + ys[cn])*W_ + xs[cn]) << 6)
                                    : g_xnhwc;
                float4 c = *(const float4*)(bp + c4*4);
                ax += wv*c.x; ay += wv*c.y; az += wv*c.z; aw += wv*c.w;
            }
            *(float4*)(val_s + p*AST + c4*4) = make_float4(ax, ay, az, aw);
        }
        __syncthreads();

        // ---- GEMM chunk via mma.sync bf16 m16n8k16 (3-term split) ----
#pragma unroll
        for (int kq = 0; kq < 4; kq++) {
            int c0 = kq*16;
            uint32_t ahi[2][4], alo[2][4];
#pragma unroll
            for (int mi = 0; mi < 2; mi++) {
                int r0 = warp*32 + mi*16 + g;
                float2 v00 = *(const float2*)(val_s + r0*AST     + c0 + 2*t);
                float2 v10 = *(const float2*)(val_s + (r0+8)*AST + c0 + 2*t);
                float2 v01 = *(const float2*)(val_s + r0*AST     + c0 + 2*t + 8);
                float2 v11 = *(const float2*)(val_s + (r0+8)*AST + c0 + 2*t + 8);
                ahi[mi][0] = pack_hi(v00.x, v00.y); alo[mi][0] = pack_lo(v00.x, v00.y);
                ahi[mi][1] = pack_hi(v10.x, v10.y); alo[mi][1] = pack_lo(v10.x, v10.y);
                ahi[mi][2] = pack_hi(v01.x, v01.y); alo[mi][2] = pack_lo(v01.x, v01.y);
                ahi[mi][3] = pack_hi(v11.x, v11.y); alo[mi][3] = pack_lo(v11.x, v11.y);
            }
#pragma unroll
            for (int ni = 0; ni < 8; ni++) {
                uint32_t bh0 = whb[(kq*8 + t)*WPR     + ni*8 + g];
                uint32_t bh1 = whb[(kq*8 + t + 4)*WPR + ni*8 + g];
                uint32_t bl0 = wlb[(kq*8 + t)*WPR     + ni*8 + g];
                uint32_t bl1 = wlb[(kq*8 + t + 4)*WPR + ni*8 + g];
                mma_bf16(acc[0][ni], ahi[0], bh0, bh1);
                mma_bf16(acc[1][ni], ahi[1], bh0, bh1);
                mma_bf16(acc[0][ni], ahi[0], bl0, bl1);
                mma_bf16(acc[1][ni], ahi[1], bl0, bl1);
                mma_bf16(acc[0][ni], alo[0], bh0, bh1);
                mma_bf16(acc[1][ni], alo[1], bh0, bh1);
            }
        }
    }

    // ---- epilogue: stage [o][p] (stride 260), psum + coalesced store ----
    __syncthreads();
    float* stg = val_s;                          // 64*260 = 16640 <= 256*68
#pragma unroll
    for (int mi = 0; mi < 2; mi++)
#pragma unroll
        for (int ni = 0; ni < 8; ni++) {
            int o = ni*8 + 2*t;
            int r = warp*32 + mi*16 + g;
            stg[o*260 + r]         = acc[mi][ni][0];
            stg[(o+1)*260 + r]     = acc[mi][ni][1];
            stg[o*260 + r + 8]     = acc[mi][ni][2];
            stg[(o+1)*260 + r + 8] = acc[mi][ni][3];
        }
    __syncthreads();

    // per-(block,o) partial sums for instance norm (deterministic, no atomics)
    {
        int o = tid >> 2;
        int q = tid & 3;
        const float* base = stg + o*260 + q*64;
        float s = 0.f, ss = 0.f;
#pragma unroll
        for (int i = 0; i < 64; i++) { float v = base[i]; s += v; ss += v*v; }
        s  += __shfl_xor_sync(~0u, s, 1);  ss += __shfl_xor_sync(~0u, ss, 1);
        s  += __shfl_xor_sync(~0u, s, 2);  ss += __shfl_xor_sync(~0u, ss, 2);
        if (q == 0) {
            int blk = rem0 / PXB;
            g_psum[(b*O_ + o)*NBLK + blk] = make_float2(s, ss);
        }
    }

#pragma unroll 1
    for (int o = 0; o < 64; o++)
        out[(b*O_ + o)*HW_ + rem0 + tid] = stg[o*260 + tid];
}

// ------- kernel 4: reduce partials, then normalize + ReLU in-place -------
__global__ void __launch_bounds__(256) k_inorm(float* __restrict__ out) {
    int bo = blockIdx.x;
    float s = 0.f, ss = 0.f;
    for (int i = threadIdx.x; i < NBLK; i += 256) {
        float2 v = g_psum[bo*NBLK + i];
        s += v.x; ss += v.y;
    }
#pragma unroll
    for (int off = 16; off; off >>= 1) {
        s  += __shfl_xor_sync(~0u, s,  off);
        ss += __shfl_xor_sync(~0u, ss, off);
    }
    __shared__ float rs[8], rss[8];
    __shared__ float mu_s, rstd_s;
    if ((threadIdx.x & 31) == 0) { rs[threadIdx.x>>5] = s; rss[threadIdx.x>>5] = ss; }
    __syncthreads();
    if (threadIdx.x == 0) {
        float S = 0.f, SS = 0.f;
#pragma unroll
        for (int i = 0; i < 8; i++) { S += rs[i]; SS += rss[i]; }
        float mu  = S / (float)HW_;
        float var = SS / (float)HW_ - mu*mu;
        mu_s = mu;
        rstd_s = rsqrtf(var + EPS_);
    }
    __syncthreads();
    float mu = mu_s, rstd = rstd_s;
    float4* row = (float4*)(out + bo*HW_);
    for (int i = threadIdx.x; i < HW_/4; i += 256) {
        float4 v = row[i];
        v.x = fmaxf((v.x - mu)*rstd, 0.f);
        v.y = fmaxf((v.y - mu)*rstd, 0.f);
        v.z = fmaxf((v.z - mu)*rstd, 0.f);
        v.w = fmaxf((v.w - mu)*rstd, 0.f);
        row[i] = v;
    }
}

// ---------------- launch ----------------
extern "C" void kernel_launch(void* const* d_in, const int* in_sizes, int n_in,
                              void* d_out, int out_size) {
    (void)in_sizes; (void)n_in; (void)out_size;
    const float* x     = (const float*)d_in[0];
    const float* dw_w  = (const float*)d_in[1];
    const float* dw_b  = (const float*)d_in[2];
    const float* bn_g  = (const float*)d_in[3];
    const float* bn_b  = (const float*)d_in[4];
    const float* bn_m  = (const float*)d_in[5];
    const float* bn_v  = (const float*)d_in[6];
    const float* pw_w  = (const float*)d_in[7];
    const float* pw_b  = (const float*)d_in[8];
    const float* dcn_w = (const float*)d_in[9];
    // d_in[10] = dcn_b: exactly cancelled by the instance norm -> unused.
    float* out = (float*)d_out;

    cudaFuncSetAttribute(k_main, cudaFuncAttributeMaxDynamicSharedMemorySize, SMEM_BYTES);

    k_transpose<<<dim3((W_/32)*(C_/32), H_, B_), dim3(32, 8)>>>(x);
    k_wprep<<<((J_/2)*O_ + 255)/256, 256>>>(dcn_w);
    k_offsets<<<(B_*HW_)/32, 256>>>(dw_w, dw_b, bn_g, bn_b, bn_m, bn_v, pw_w, pw_b);
    k_main<<<NP_/PXB, 256, SMEM_BYTES>>>(out);
    k_inorm<<<B_*O_, 256>>>(out);
}

// round 16
// speedup vs baseline: 1.3189x; 1.1260x over previous
#include <cuda_runtime.h>
#include <cstdint>

#define B_   2
#define C_   64
#define H_   192
#define W_   192
#define HW_  (H_*W_)
#define NP_  (B_*HW_)
#define O_   64
#define K_   9
#define J_   576
#define EPS_ 1e-5f
#define PXB  256                   // pixels per k_main block
#define NBLK (HW_/PXB)             // k_main blocks per batch image (144)

// ---------------- scratch (no allocations allowed) ----------------
__device__ float    g_xnhwc[B_*HW_*C_];  // x transposed to [B][H][W][C]
__device__ float    g_off[27*NP_];       // planar: [slot][pixel]
__device__ uint32_t g_wb_hi[(J_/2)*O_];  // W bf16-hi pairs: [tap][cpair][o]
__device__ uint32_t g_wb_lo[(J_/2)*O_];  // W bf16-lo residual pairs
__device__ float2   g_psum[B_*O_*NBLK];  // per-(b,o,block) partial (sum, sumsq)

// pack (top16(a), top16(b)) -> bf16x2 {lo=a_hi16, hi=b_hi16} (RZ truncation)
__device__ __forceinline__ uint32_t pack_hi(float a, float b) {
    uint32_t d;
    asm("prmt.b32 %0, %1, %2, 0x7632;"
        : "=r"(d) : "r"(__float_as_uint(a)), "r"(__float_as_uint(b)));
    return d;
}
// pack residuals (a - bf16rz(a), b - bf16rz(b)) -> bf16x2 (RN)
__device__ __forceinline__ uint32_t pack_lo(float a, float b) {
    float la = a - __uint_as_float(__float_as_uint(a) & 0xffff0000u);
    float lb = b - __uint_as_float(__float_as_uint(b) & 0xffff0000u);
    uint32_t d;
    asm("cvt.rn.bf16x2.f32 %0, %1, %2;" : "=r"(d) : "f"(lb), "f"(la));
    return d;
}
__device__ __forceinline__ void mma_bf16(float* c, const uint32_t* a, uint32_t b0, uint32_t b1) {
    asm volatile(
        "mma.sync.aligned.m16n8k16.row.col.f32.bf16.bf16.f32 "
        "{%0,%1,%2,%3}, {%4,%5,%6,%7}, {%8,%9}, {%0,%1,%2,%3};"
        : "+f"(c[0]), "+f"(c[1]), "+f"(c[2]), "+f"(c[3])
        : "r"(a[0]), "r"(a[1]), "r"(a[2]), "r"(a[3]),
          "r"(b0),  "r"(b1));
}

// ---------------- kernel 0: NCHW -> NHWC transpose ----------------
__global__ void k_transpose(const float* __restrict__ x) {
    __shared__ float t[32][33];
    int xt = blockIdx.x % (W_/32);
    int ct = blockIdx.x / (W_/32);
    int y  = blockIdx.y, b = blockIdx.z;
    int tx = threadIdx.x, ty = threadIdx.y;
#pragma unroll
    for (int i = 0; i < 4; i++) {
        int c  = ct*32 + ty + i*8;
        int xx = xt*32 + tx;
        t[ty + i*8][tx] = x[((b*C_ + c)*H_ + y)*W_ + xx];
    }
    __syncthreads();
#pragma unroll
    for (int i = 0; i < 4; i++) {
        int xx = xt*32 + ty + i*8;
        int c  = ct*32 + tx;
        g_xnhwc[(((b*H_ + y)*W_ + xx) << 6) + c] = t[tx][ty + i*8];
    }
}

// ------ kernel 1: dcn_w -> per-tap channel-pair-packed bf16 hi/lo ------
__global__ void k_wprep(const float* __restrict__ dcn_w) {
    int t = blockIdx.x*256 + threadIdx.x;     // t = jp*64 + o
    if (t < (J_/2)*O_) {
        int o   = t & 63;
        int jp  = t >> 6;        // global pair index
        int tap = jp >> 5;
        int cp  = jp & 31;
        int c0  = cp*2;
        float v0 = dcn_w[o*J_ + c0*K_ + tap];
        float v1 = dcn_w[o*J_ + (c0+1)*K_ + tap];
        g_wb_hi[t] = pack_hi(v0, v1);
        g_wb_lo[t] = pack_lo(v0, v1);
    }
}

// ------- kernel 2: dwconv + BN + ReLU + 1x1 -> offsets / mask -------
__global__ void __launch_bounds__(256) k_offsets(
    const float* __restrict__ dw_w, const float* __restrict__ dw_b,
    const float* __restrict__ bn_g, const float* __restrict__ bn_b,
    const float* __restrict__ bn_m, const float* __restrict__ bn_v,
    const float* __restrict__ pw_w, const float* __restrict__ pw_b)
{
    __shared__ float xt[3*34*64];
    __shared__ float hs[32*64];
    __shared__ float4 ws[16*27];
    __shared__ float pb[27];

    int tid = threadIdx.x;
    int gp0 = blockIdx.x * 32;
    int b   = gp0 / HW_;
    int rem = gp0 % HW_;
    int y   = rem / W_;
    int x0  = rem % W_;

    for (int e4 = tid; e4 < 3*34*16; e4 += 256) {
        int c4 = e4 & 15;
        int t2 = e4 >> 4;
        int xi = t2 % 34;
        int r  = t2 / 34;
        int yy = y - 1 + r;
        int xx = x0 - 1 + xi;
        float4 v = make_float4(0.f, 0.f, 0.f, 0.f);
        if ((unsigned)yy < H_ && (unsigned)xx < W_)
            v = *(const float4*)(g_xnhwc + (((b*H_ + yy)*W_ + xx) << 6) + c4*4);
        ((float4*)xt)[e4] = v;
    }
    for (int e = tid; e < 16*27; e += 256) {
        int o  = e % 27;
        int i4 = e / 27;
        const float* src = pw_w + o*64 + i4*4;
        ws[e] = make_float4(src[0], src[1], src[2], src[3]);
    }
    if (tid < 27) pb[tid] = pw_b[tid];
    __syncthreads();

#pragma unroll
    for (int i = 0; i < 8; i++) {
        int e = tid + i*256;
        int c = e & 63;
        int p = e >> 6;
        float acc = 0.f;
#pragma unroll
        for (int ky = 0; ky < 3; ky++) {
#pragma unroll
            for (int kx = 0; kx < 3; kx++) {
                acc += dw_w[c*9 + ky*3 + kx] * xt[(ky*34 + (p + kx))*64 + c];
            }
        }
        float s = bn_g[c] * rsqrtf(bn_v[c] + EPS_);
        hs[e] = fmaxf((acc + dw_b[c] - bn_m[c]) * s + bn_b[c], 0.f);
    }
    __syncthreads();

    for (int e = tid; e < 32*27; e += 256) {
        int p = e / 27;
        int o = e - p*27;
        float om = pb[o];
        const float4* hv = (const float4*)(hs + p*64);
#pragma unroll
        for (int i4 = 0; i4 < 16; i4++) {
            float4 h4 = hv[i4];
            float4 w4 = ws[i4*27 + o];
            om += h4.x*w4.x + h4.y*w4.y + h4.z*w4.z + h4.w*w4.w;
        }
        int slot;
        float v;
        if (o < 18) { slot = (o & 1)*9 + (o >> 1); v = om; }
        else        { slot = o; v = 1.f / (1.f + expf(-om)); }
        g_off[slot*NP_ + gp0 + p] = v;
    }
}

// ------- kernel 3: deformable gather + bf16-split mma projection -------
// 256 px x 64 o per block, 9 taps of K=64; split-bf16 (hi/lo), m16n8k16.
#define AST 68                                   // val_s row stride (floats)
#define WPR 72                                   // W pair-row stride (uint32)
#define SMEM_FLOATS (PXB*AST + 2*32*WPR)
#define SMEM_BYTES  (SMEM_FLOATS*4)

__global__ void __launch_bounds__(256, 2) k_main(float* __restrict__ out) {
    extern __shared__ __align__(16) float sm[];
    float*    val_s = sm;                                  // [p][c], stride AST
    uint32_t* whb   = (uint32_t*)(sm + PXB*AST);           // [cpair][o] hi
    uint32_t* wlb   = whb + 32*WPR;                        // [cpair][o] lo

    int tid  = threadIdx.x;
    int lane = tid & 31;
    int warp = tid >> 5;
    int g    = lane >> 2;                        // fragment group 0..7
    int t    = lane & 3;                         // thread-in-group 0..3
    int gp0  = blockIdx.x * PXB;
    int b    = gp0 / HW_;
    int rem0 = gp0 % HW_;

    int c4 = tid & 15;                           // gather: channel quad
    int pi = tid >> 4;                           // gather: pixel sub-index

    // incremental pixel coords for p = it*16 + pi (advance by 16 per it)
    int cy0 = (rem0 + pi) / W_;
    int cx0 = (rem0 + pi) % W_;

    float acc[2][8][4];
#pragma unroll
    for (int mi = 0; mi < 2; mi++)
#pragma unroll
        for (int ni = 0; ni < 8; ni++)
#pragma unroll
            for (int r = 0; r < 4; r++) acc[mi][ni][r] = 0.f;

#pragma unroll 1
    for (int k = 0; k < 9; k++) {
        if (k) __syncthreads();                  // prev GEMM done with smem

        // ---- load W hi/lo pair-chunks [32 pairs][64 o] (stride 72) ----
        for (int e = tid; e < 32*16; e += 256) {
            int row  = e >> 4;
            int quad = e & 15;
            *(uint4*)(whb + row*WPR + quad*4) =
                *(const uint4*)(g_wb_hi + k*2048 + row*64 + quad*4);
            *(uint4*)(wlb + row*WPR + quad*4) =
                *(const uint4*)(g_wb_lo + k*2048 + row*64 + quad*4);
        }

        // ---- gather this tap: 16 lanes per pixel (one float4 each) ----
        int ky = k/3 - 1, kx = k%3 - 1;
        const float* o1 = g_off + k*NP_     + gp0 + pi;
        const float* o2 = g_off + (9+k)*NP_ + gp0 + pi;
        const float* o3 = g_off + (18+k)*NP_+ gp0 + pi;
        int cy = cy0, cx = cx0;
#pragma unroll 2
        for (int it = 0; it < PXB/16; it++) {
            int p = it*16 + pi;

            float dy = o1[it*16];
            float dx = o2[it*16];
            float m  = o3[it*16];
            float py = (float)(cy + ky) + dy;
            float px = (float)(cx + kx) + dx;
            float fy0 = floorf(py), fx0 = floorf(px);
            float wy1 = py - fy0,   wx1 = px - fx0;
            float wy0 = 1.f - wy1,  wx0 = 1.f - wx1;
            int   iy  = (int)fy0,   ix  = (int)fx0;

            float wts[4] = { wy0*wx0*m, wy0*wx1*m, wy1*wx0*m, wy1*wx1*m };
            int   ys[4]  = { iy, iy, iy+1, iy+1 };
            int   xs[4]  = { ix, ix+1, ix, ix+1 };

            float ax = 0.f, ay = 0.f, az = 0.f, aw = 0.f;
#pragma unroll
            for (int cn = 0; cn < 4; cn++) {
                bool v = (unsigned)ys[cn] < H_ && (unsigned)xs[cn] < W_;
                float wv = v ? wts[cn] : 0.f;
                const float* bp = v ? g_xnhwc + (((b*H_ + ys[cn])*W_ + xs[cn]) << 6)
                                    : g_xnhwc;
                float4 c = *(const float4*)(bp + c4*4);
                ax += wv*c.x; ay += wv*c.y; az += wv*c.z; aw += wv*c.w;
            }
            *(float4*)(val_s + p*AST + c4*4) = make_float4(ax, ay, az, aw);

            cx += 16;
            if (cx >= W_) { cx -= W_; cy++; }
        }
        __syncthreads();

        // ---- GEMM chunk via mma.sync bf16 m16n8k16 (3-term split) ----
#pragma unroll
        for (int kq = 0; kq < 4; kq++) {
            int c0 = kq*16;
            uint32_t ahi[2][4], alo[2][4];
#pragma unroll
            for (int mi = 0; mi < 2; mi++) {
                int r0 = warp*32 + mi*16 + g;
                float2 v00 = *(const float2*)(val_s + r0*AST     + c0 + 2*t);
                float2 v10 = *(const float2*)(val_s + (r0+8)*AST + c0 + 2*t);
                float2 v01 = *(const float2*)(val_s + r0*AST     + c0 + 2*t + 8);
                float2 v11 = *(const float2*)(val_s + (r0+8)*AST + c0 + 2*t + 8);
                ahi[mi][0] = pack_hi(v00.x, v00.y); alo[mi][0] = pack_lo(v00.x, v00.y);
                ahi[mi][1] = pack_hi(v10.x, v10.y); alo[mi][1] = pack_lo(v10.x, v10.y);
                ahi[mi][2] = pack_hi(v01.x, v01.y); alo[mi][2] = pack_lo(v01.x, v01.y);
                ahi[mi][3] = pack_hi(v11.x, v11.y); alo[mi][3] = pack_lo(v11.x, v11.y);
            }
#pragma unroll
            for (int ni = 0; ni < 8; ni++) {
                uint32_t bh0 = whb[(kq*8 + t)*WPR     + ni*8 + g];
                uint32_t bh1 = whb[(kq*8 + t + 4)*WPR + ni*8 + g];
                uint32_t bl0 = wlb[(kq*8 + t)*WPR     + ni*8 + g];
                uint32_t bl1 = wlb[(kq*8 + t + 4)*WPR + ni*8 + g];
                mma_bf16(acc[0][ni], ahi[0], bh0, bh1);
                mma_bf16(acc[1][ni], ahi[1], bh0, bh1);
                mma_bf16(acc[0][ni], ahi[0], bl0, bl1);
                mma_bf16(acc[1][ni], ahi[1], bl0, bl1);
                mma_bf16(acc[0][ni], alo[0], bh0, bh1);
                mma_bf16(acc[1][ni], alo[1], bh0, bh1);
            }
        }
    }

    // ---- epilogue: stage [o][p] (stride 260), psum + coalesced store ----
    __syncthreads();
    float* stg = val_s;                          // 64*260 = 16640 <= 256*68
#pragma unroll
    for (int mi = 0; mi < 2; mi++)
#pragma unroll
        for (int ni = 0; ni < 8; ni++) {
            int o = ni*8 + 2*t;
            int r = warp*32 + mi*16 + g;
            stg[o*260 + r]         = acc[mi][ni][0];
            stg[(o+1)*260 + r]     = acc[mi][ni][1];
            stg[o*260 + r + 8]     = acc[mi][ni][2];
            stg[(o+1)*260 + r + 8] = acc[mi][ni][3];
        }
    __syncthreads();

    // per-(block,o) partial sums for instance norm (deterministic, no atomics)
    {
        int o = tid >> 2;
        int q = tid & 3;
        const float* base = stg + o*260 + q*64;
        float s = 0.f, ss = 0.f;
#pragma unroll
        for (int i = 0; i < 64; i++) { float v = base[i]; s += v; ss += v*v; }
        s  += __shfl_xor_sync(~0u, s, 1);  ss += __shfl_xor_sync(~0u, ss, 1);
        s  += __shfl_xor_sync(~0u, s, 2);  ss += __shfl_xor_sync(~0u, ss, 2);
        if (q == 0) {
            int blk = rem0 / PXB;
            g_psum[(b*O_ + o)*NBLK + blk] = make_float2(s, ss);
        }
    }

    // vectorized store: 16 iterations of float4
#pragma unroll
    for (int r = 0; r < 16; r++) {
        int e = r*256 + tid;
        int o = e >> 6;
        int q = e & 63;
        float4 v = *(const float4*)(stg + o*260 + q*4);
        *(float4*)(out + (b*O_ + o)*HW_ + rem0 + q*4) = v;
    }
}

// ------- kernel 4: reduce partials, then normalize + ReLU in-place -------
__global__ void __launch_bounds__(256) k_inorm(float* __restrict__ out) {
    int bo = blockIdx.x;
    float s = 0.f, ss = 0.f;
    for (int i = threadIdx.x; i < NBLK; i += 256) {
        float2 v = g_psum[bo*NBLK + i];
        s += v.x; ss += v.y;
    }
#pragma unroll
    for (int off = 16; off; off >>= 1) {
        s  += __shfl_xor_sync(~0u, s,  off);
        ss += __shfl_xor_sync(~0u, ss, off);
    }
    __shared__ float rs[8], rss[8];
    __shared__ float mu_s, rstd_s;
    if ((threadIdx.x & 31) == 0) { rs[threadIdx.x>>5] = s; rss[threadIdx.x>>5] = ss; }
    __syncthreads();
    if (threadIdx.x == 0) {
        float S = 0.f, SS = 0.f;
#pragma unroll
        for (int i = 0; i < 8; i++) { S += rs[i]; SS += rss[i]; }
        float mu  = S / (float)HW_;
        float var = SS / (float)HW_ - mu*mu;
        mu_s = mu;
        rstd_s = rsqrtf(var + EPS_);
    }
    __syncthreads();
    float mu = mu_s, rstd = rstd_s;
    float4* row = (float4*)(out + bo*HW_);
    for (int i = threadIdx.x; i < HW_/4; i += 256) {
        float4 v = row[i];
        v.x = fmaxf((v.x - mu)*rstd, 0.f);
        v.y = fmaxf((v.y - mu)*rstd, 0.f);
        v.z = fmaxf((v.z - mu)*rstd, 0.f);
        v.w = fmaxf((v.w - mu)*rstd, 0.f);
        row[i] = v;
    }
}

// ---------------- launch ----------------
extern "C" void kernel_launch(void* const* d_in, const int* in_sizes, int n_in,
                              void* d_out, int out_size) {
    (void)in_sizes; (void)n_in; (void)out_size;
    const float* x     = (const float*)d_in[0];
    const float* dw_w  = (const float*)d_in[1];
    const float* dw_b  = (const float*)d_in[2];
    const float* bn_g  = (const float*)d_in[3];
    const float* bn_b  = (const float*)d_in[4];
    const float* bn_m  = (const float*)d_in[5];
    const float* bn_v  = (const float*)d_in[6];
    const float* pw_w  = (const float*)d_in[7];
    const float* pw_b  = (const float*)d_in[8];
    const float* dcn_w = (const float*)d_in[9];
    // d_in[10] = dcn_b: exactly cancelled by the instance norm -> unused.
    float* out = (float*)d_out;

    cudaFuncSetAttribute(k_main, cudaFuncAttributeMaxDynamicSharedMemorySize, SMEM_BYTES);

    k_transpose<<<dim3((W_/32)*(C_/32), H_, B_), dim3(32, 8)>>>(x);
    k_wprep<<<((J_/2)*O_ + 255)/256, 256>>>(dcn_w);
    k_offsets<<<(B_*HW_)/32, 256>>>(dw_w, dw_b, bn_g, bn_b, bn_m, bn_v, pw_w, pw_b);
    k_main<<<NP_/PXB, 256, SMEM_BYTES>>>(out);
    k_inorm<<<B_*O_, 256>>>(out);
}

// round 17
// speedup vs baseline: 1.3955x; 1.0581x over previous
#include <cuda_runtime.h>
#include <cstdint>

#define B_   2
#define C_   64
#define H_   192
#define W_   192
#define HW_  (H_*W_)
#define NP_  (B_*HW_)
#define O_   64
#define K_   9
#define J_   576
#define EPS_ 1e-5f
#define PXB  256                   // pixels per k_main block
#define NBLK (HW_/PXB)             // k_main blocks per batch image (144)

// ---------------- scratch (no allocations allowed) ----------------
__device__ float    g_xnhwc[B_*HW_*C_];  // x transposed to [B][H][W][C]
__device__ float    g_off[27*NP_];       // planar: [slot][pixel]
__device__ uint32_t g_wb_hi[(J_/2)*O_];  // W bf16-hi pairs: [tap][cpair][o]
__device__ uint32_t g_wb_lo[(J_/2)*O_];  // W bf16-lo residual pairs
__device__ float2   g_psum[B_*O_*NBLK];  // per-(b,o,block) partial (sum, sumsq)

__device__ __forceinline__ uint32_t smem_u32(const void* p) {
    uint32_t a;
    asm("{ .reg .u64 t; cvta.to.shared.u64 t, %1; cvt.u32.u64 %0, t; }" : "=r"(a) : "l"(p));
    return a;
}
__device__ __forceinline__ void cp16(uint32_t dst, const void* src) {
    asm volatile("cp.async.ca.shared.global [%0], [%1], 16;" :: "r"(dst), "l"(src));
}
// pack (top16(a), top16(b)) -> bf16x2 (RZ truncation)
__device__ __forceinline__ uint32_t pack_hi(float a, float b) {
    uint32_t d;
    asm("prmt.b32 %0, %1, %2, 0x7632;"
        : "=r"(d) : "r"(__float_as_uint(a)), "r"(__float_as_uint(b)));
    return d;
}
// pack residuals -> bf16x2 (RN)
__device__ __forceinline__ uint32_t pack_lo(float a, float b) {
    float la = a - __uint_as_float(__float_as_uint(a) & 0xffff0000u);
    float lb = b - __uint_as_float(__float_as_uint(b) & 0xffff0000u);
    uint32_t d;
    asm("cvt.rn.bf16x2.f32 %0, %1, %2;" : "=r"(d) : "f"(lb), "f"(la));
    return d;
}
__device__ __forceinline__ void mma_bf16(float* c, const uint32_t* a, uint32_t b0, uint32_t b1) {
    asm volatile(
        "mma.sync.aligned.m16n8k16.row.col.f32.bf16.bf16.f32 "
        "{%0,%1,%2,%3}, {%4,%5,%6,%7}, {%8,%9}, {%0,%1,%2,%3};"
        : "+f"(c[0]), "+f"(c[1]), "+f"(c[2]), "+f"(c[3])
        : "r"(a[0]), "r"(a[1]), "r"(a[2]), "r"(a[3]),
          "r"(b0),  "r"(b1));
}

// ---------------- kernel 0: NCHW -> NHWC transpose ----------------
__global__ void k_transpose(const float* __restrict__ x) {
    __shared__ float t[32][33];
    int xt = blockIdx.x % (W_/32);
    int ct = blockIdx.x / (W_/32);
    int y  = blockIdx.y, b = blockIdx.z;
    int tx = threadIdx.x, ty = threadIdx.y;
#pragma unroll
    for (int i = 0; i < 4; i++) {
        int c  = ct*32 + ty + i*8;
        int xx = xt*32 + tx;
        t[ty + i*8][tx] = x[((b*C_ + c)*H_ + y)*W_ + xx];
    }
    __syncthreads();
#pragma unroll
    for (int i = 0; i < 4; i++) {
        int xx = xt*32 + ty + i*8;
        int c  = ct*32 + tx;
        g_xnhwc[(((b*H_ + y)*W_ + xx) << 6) + c] = t[tx][ty + i*8];
    }
}

// ------ kernel 1: dcn_w -> per-tap channel-pair-packed bf16 hi/lo ------
__global__ void k_wprep(const float* __restrict__ dcn_w) {
    int t = blockIdx.x*256 + threadIdx.x;     // t = jp*64 + o
    if (t < (J_/2)*O_) {
        int o   = t & 63;
        int jp  = t >> 6;
        int tap = jp >> 5;
        int cp  = jp & 31;
        int c0  = cp*2;
        float v0 = dcn_w[o*J_ + c0*K_ + tap];
        float v1 = dcn_w[o*J_ + (c0+1)*K_ + tap];
        g_wb_hi[t] = pack_hi(v0, v1);
        g_wb_lo[t] = pack_lo(v0, v1);
    }
}

// ------- kernel 2: dwconv + BN + ReLU + 1x1 -> offsets / mask -------
__global__ void __launch_bounds__(256) k_offsets(
    const float* __restrict__ dw_w, const float* __restrict__ dw_b,
    const float* __restrict__ bn_g, const float* __restrict__ bn_b,
    const float* __restrict__ bn_m, const float* __restrict__ bn_v,
    const float* __restrict__ pw_w, const float* __restrict__ pw_b)
{
    __shared__ float xt[3*34*64];
    __shared__ float hs[32*64];
    __shared__ float4 ws[16*27];
    __shared__ float pb[27];

    int tid = threadIdx.x;
    int gp0 = blockIdx.x * 32;
    int b   = gp0 / HW_;
    int rem = gp0 % HW_;
    int y   = rem / W_;
    int x0  = rem % W_;

    for (int e4 = tid; e4 < 3*34*16; e4 += 256) {
        int c4 = e4 & 15;
        int t2 = e4 >> 4;
        int xi = t2 % 34;
        int r  = t2 / 34;
        int yy = y - 1 + r;
        int xx = x0 - 1 + xi;
        float4 v = make_float4(0.f, 0.f, 0.f, 0.f);
        if ((unsigned)yy < H_ && (unsigned)xx < W_)
            v = *(const float4*)(g_xnhwc + (((b*H_ + yy)*W_ + xx) << 6) + c4*4);
        ((float4*)xt)[e4] = v;
    }
    for (int e = tid; e < 16*27; e += 256) {
        int o  = e % 27;
        int i4 = e / 27;
        const float* src = pw_w + o*64 + i4*4;
        ws[e] = make_float4(src[0], src[1], src[2], src[3]);
    }
    if (tid < 27) pb[tid] = pw_b[tid];
    __syncthreads();

#pragma unroll
    for (int i = 0; i < 8; i++) {
        int e = tid + i*256;
        int c = e & 63;
        int p = e >> 6;
        float acc = 0.f;
#pragma unroll
        for (int ky = 0; ky < 3; ky++) {
#pragma unroll
            for (int kx = 0; kx < 3; kx++) {
                acc += dw_w[c*9 + ky*3 + kx] * xt[(ky*34 + (p + kx))*64 + c];
            }
        }
        float s = bn_g[c] * rsqrtf(bn_v[c] + EPS_);
        hs[e] = fmaxf((acc + dw_b[c] - bn_m[c]) * s + bn_b[c], 0.f);
    }
    __syncthreads();

    for (int e = tid; e < 32*27; e += 256) {
        int p = e / 27;
        int o = e - p*27;
        float om = pb[o];
        const float4* hv = (const float4*)(hs + p*64);
#pragma unroll
        for (int i4 = 0; i4 < 16; i4++) {
            float4 h4 = hv[i4];
            float4 w4 = ws[i4*27 + o];
            om += h4.x*w4.x + h4.y*w4.y + h4.z*w4.z + h4.w*w4.w;
        }
        int slot;
        float v;
        if (o < 18) { slot = (o & 1)*9 + (o >> 1); v = om; }
        else        { slot = o; v = 1.f / (1.f + expf(-om)); }
        g_off[slot*NP_ + gp0 + p] = v;
    }
}

// ------- kernel 3: deformable gather + bf16-split mma projection -------
// 256 px x 64 o per block, 9 taps of K=64; split-bf16 m16n8k16;
// cp.async double-buffered W tiles + offset slices.
#define AST 68                                   // val_s row stride (floats)
#define WPR 72                                   // W pair-row stride (uint32)
#define VAL_FLOATS (PXB*AST)                     // 17408
#define WBUF_U32   (2*32*WPR)                    // hi+lo per buffer = 4608
#define OFF_FLOATS 768                           // 3 x 256 per buffer
#define SMEM_FLOATS (VAL_FLOATS + 2*WBUF_U32 + 2*OFF_FLOATS)
#define SMEM_BYTES  (SMEM_FLOATS*4)

__global__ void __launch_bounds__(256, 2) k_main(float* __restrict__ out) {
    extern __shared__ __align__(16) float sm[];
    float*    val_s  = sm;                               // [p][c], stride AST
    uint32_t* wbase  = (uint32_t*)(sm + VAL_FLOATS);     // 2 x (hi 2304 | lo 2304)
    float*    offb0  = sm + VAL_FLOATS + 2*WBUF_U32;     // 2 x [3][256]
    uint32_t  wsm    = smem_u32(wbase);
    uint32_t  osm    = smem_u32(offb0);

    int tid  = threadIdx.x;
    int lane = tid & 31;
    int warp = tid >> 5;
    int g    = lane >> 2;                        // fragment group 0..7
    int t    = lane & 3;                         // thread-in-group 0..3
    int gp0  = blockIdx.x * PXB;
    int b    = gp0 / HW_;
    int rem0 = gp0 % HW_;

    int c8g = tid & 7;                           // gather: channel octet (8 ch)
    int pig = tid >> 3;                          // gather: pixel 0..31
    int cy0 = (rem0 + pig) / W_;
    int cx0 = (rem0 + pig) % W_;

    float acc[2][8][4];
#pragma unroll
    for (int mi = 0; mi < 2; mi++)
#pragma unroll
        for (int ni = 0; ni < 8; ni++)
#pragma unroll
            for (int r = 0; r < 4; r++) acc[mi][ni][r] = 0.f;

    // ---- prefetch tap 0 (W hi/lo + offsets) ----
    {
        // W: 512 float4 for hi + 512 for lo; 2 each per thread
#pragma unroll
        for (int r = 0; r < 2; r++) {
            int e    = tid + r*256;
            int row  = e >> 4;
            int quad = e & 15;
            uint32_t off = (uint32_t)(row*WPR + quad*4) * 4u;
            cp16(wsm + off,              g_wb_hi + row*64 + quad*4);
            cp16(wsm + 2304u*4u + off,   g_wb_lo + row*64 + quad*4);
        }
        if (tid < 192) {
            int slot = tid >> 6;                 // 0..2
            int wi   = tid & 63;
            int sidx = (slot == 0) ? 0 : (slot == 1) ? 9 : 18;
            cp16(osm + (uint32_t)(slot*256 + wi*4)*4u,
                 g_off + sidx*NP_ + gp0 + wi*4);
        }
        asm volatile("cp.async.commit_group;");
    }

#pragma unroll 1
    for (int k = 0; k < 9; k++) {
        int cur = k & 1;
        int nxt = cur ^ 1;
        asm volatile("cp.async.wait_group 0;");
        __syncthreads();                         // prefetch visible + prev GEMM done

        // ---- gather this tap: 8 lanes per pixel (two float4 each) ----
        {
            int ky = k/3 - 1, kx = k%3 - 1;
            const float* offc = offb0 + cur*OFF_FLOATS;
            int cy = cy0, cx = cx0;
#pragma unroll 1
            for (int it = 0; it < 8; it++) {
                int p  = it*32 + pig;
                float dy = offc[p];
                float dx = offc[256 + p];
                float m  = offc[512 + p];
                float py = (float)(cy + ky) + dy;
                float px = (float)(cx + kx) + dx;
                float fy0 = floorf(py), fx0 = floorf(px);
                float wy1 = py - fy0,   wx1 = px - fx0;
                float wy0 = 1.f - wy1,  wx0 = 1.f - wx1;
                int   iy  = (int)fy0,   ix  = (int)fx0;

                float wts[4] = { wy0*wx0*m, wy0*wx1*m, wy1*wx0*m, wy1*wx1*m };
                int   ys[4]  = { iy, iy, iy+1, iy+1 };
                int   xs[4]  = { ix, ix+1, ix, ix+1 };

                float4 A0 = make_float4(0.f,0.f,0.f,0.f);
                float4 A1 = make_float4(0.f,0.f,0.f,0.f);
#pragma unroll
                for (int cn = 0; cn < 4; cn++) {
                    bool v = (unsigned)ys[cn] < H_ && (unsigned)xs[cn] < W_;
                    float wv = v ? wts[cn] : 0.f;
                    const float* bp = v ? g_xnhwc + (((b*H_ + ys[cn])*W_ + xs[cn]) << 6)
                                        : g_xnhwc;
                    const float4* src = (const float4*)(bp + c8g*8);
                    float4 c0 = src[0], c1 = src[1];
                    A0.x += wv*c0.x; A0.y += wv*c0.y; A0.z += wv*c0.z; A0.w += wv*c0.w;
                    A1.x += wv*c1.x; A1.y += wv*c1.y; A1.z += wv*c1.z; A1.w += wv*c1.w;
                }
                float4* dst = (float4*)(val_s + p*AST + c8g*8);
                dst[0] = A0; dst[1] = A1;

                cx += 32;
                if (cx >= W_) { cx -= W_; cy++; }
            }
        }

        // ---- prefetch tap k+1 while GEMM(k) runs ----
        if (k < 8) {
            uint32_t wdst = wsm + (uint32_t)nxt * (WBUF_U32*4u);
#pragma unroll
            for (int r = 0; r < 2; r++) {
                int e    = tid + r*256;
                int row  = e >> 4;
                int quad = e & 15;
                uint32_t off = (uint32_t)(row*WPR + quad*4) * 4u;
                cp16(wdst + off,            g_wb_hi + (k+1)*2048 + row*64 + quad*4);
                cp16(wdst + 2304u*4u + off, g_wb_lo + (k+1)*2048 + row*64 + quad*4);
            }
            if (tid < 192) {
                int slot = tid >> 6;
                int wi   = tid & 63;
                int sidx = (slot == 0) ? (k+1) : (slot == 1) ? (k+10) : (k+19);
                cp16(osm + (uint32_t)(nxt*OFF_FLOATS + slot*256 + wi*4)*4u,
                     g_off + sidx*NP_ + gp0 + wi*4);
            }
            asm volatile("cp.async.commit_group;");
        }
        __syncthreads();                         // val ready

        // ---- GEMM chunk via mma.sync bf16 m16n8k16 (3-term split) ----
        const uint32_t* whb = wbase + cur*WBUF_U32;
        const uint32_t* wlb = whb + 2304;
#pragma unroll
        for (int kq = 0; kq < 4; kq++) {
            int c0 = kq*16;
            uint32_t ahi[2][4], alo[2][4];
#pragma unroll
            for (int mi = 0; mi < 2; mi++) {
                int r0 = warp*32 + mi*16 + g;
                float2 v00 = *(const float2*)(val_s + r0*AST     + c0 + 2*t);
                float2 v10 = *(const float2*)(val_s + (r0+8)*AST + c0 + 2*t);
                float2 v01 = *(const float2*)(val_s + r0*AST     + c0 + 2*t + 8);
                float2 v11 = *(const float2*)(val_s + (r0+8)*AST + c0 + 2*t + 8);
                ahi[mi][0] = pack_hi(v00.x, v00.y); alo[mi][0] = pack_lo(v00.x, v00.y);
                ahi[mi][1] = pack_hi(v10.x, v10.y); alo[mi][1] = pack_lo(v10.x, v10.y);
                ahi[mi][2] = pack_hi(v01.x, v01.y); alo[mi][2] = pack_lo(v01.x, v01.y);
                ahi[mi][3] = pack_hi(v11.x, v11.y); alo[mi][3] = pack_lo(v11.x, v11.y);
            }
#pragma unroll
            for (int ni = 0; ni < 8; ni++) {
                uint32_t bh0 = whb[(kq*8 + t)*WPR     + ni*8 + g];
                uint32_t bh1 = whb[(kq*8 + t + 4)*WPR + ni*8 + g];
                uint32_t bl0 = wlb[(kq*8 + t)*WPR     + ni*8 + g];
                uint32_t bl1 = wlb[(kq*8 + t + 4)*WPR + ni*8 + g];
                mma_bf16(acc[0][ni], ahi[0], bh0, bh1);
                mma_bf16(acc[1][ni], ahi[1], bh0, bh1);
                mma_bf16(acc[0][ni], ahi[0], bl0, bl1);
                mma_bf16(acc[1][ni], ahi[1], bl0, bl1);
                mma_bf16(acc[0][ni], alo[0], bh0, bh1);
                mma_bf16(acc[1][ni], alo[1], bh0, bh1);
            }
        }
    }

    // ---- epilogue: stage [o][p] (stride 260), psum + coalesced store ----
    __syncthreads();
    float* stg = val_s;                          // 64*260 = 16640 <= 17408
#pragma unroll
    for (int mi = 0; mi < 2; mi++)
#pragma unroll
        for (int ni = 0; ni < 8; ni++) {
            int o = ni*8 + 2*t;
            int r = warp*32 + mi*16 + g;
            stg[o*260 + r]         = acc[mi][ni][0];
            stg[(o+1)*260 + r]     = acc[mi][ni][1];
            stg[o*260 + r + 8]     = acc[mi][ni][2];
            stg[(o+1)*260 + r + 8] = acc[mi][ni][3];
        }
    __syncthreads();

    // per-(block,o) partial sums for instance norm (deterministic, no atomics)
    {
        int o = tid >> 2;
        int q = tid & 3;
        const float* base = stg + o*260 + q*64;
        float s = 0.f, ss = 0.f;
#pragma unroll
        for (int i = 0; i < 64; i++) { float v = base[i]; s += v; ss += v*v; }
        s  += __shfl_xor_sync(~0u, s, 1);  ss += __shfl_xor_sync(~0u, ss, 1);
        s  += __shfl_xor_sync(~0u, s, 2);  ss += __shfl_xor_sync(~0u, ss, 2);
        if (q == 0) {
            int blk = rem0 / PXB;
            g_psum[(b*O_ + o)*NBLK + blk] = make_float2(s, ss);
        }
    }

    // vectorized store: 16 iterations of float4
#pragma unroll
    for (int r = 0; r < 16; r++) {
        int e = r*256 + tid;
        int o = e >> 6;
        int q = e & 63;
        float4 v = *(const float4*)(stg + o*260 + q*4);
        *(float4*)(out + (b*O_ + o)*HW_ + rem0 + q*4) = v;
    }
}

// ------- kernel 4: reduce partials, then normalize + ReLU in-place -------
__global__ void __launch_bounds__(256) k_inorm(float* __restrict__ out) {
    int bo = blockIdx.x;
    float s = 0.f, ss = 0.f;
    for (int i = threadIdx.x; i < NBLK; i += 256) {
        float2 v = g_psum[bo*NBLK + i];
        s += v.x; ss += v.y;
    }
#pragma unroll
    for (int off = 16; off; off >>= 1) {
        s  += __shfl_xor_sync(~0u, s,  off);
        ss += __shfl_xor_sync(~0u, ss, off);
    }
    __shared__ float rs[8], rss[8];
    __shared__ float mu_s, rstd_s;
    if ((threadIdx.x & 31) == 0) { rs[threadIdx.x>>5] = s; rss[threadIdx.x>>5] = ss; }
    __syncthreads();
    if (threadIdx.x == 0) {
        float S = 0.f, SS = 0.f;
#pragma unroll
        for (int i = 0; i < 8; i++) { S += rs[i]; SS += rss[i]; }
        float mu  = S / (float)HW_;
        float var = SS / (float)HW_ - mu*mu;
        mu_s = mu;
        rstd_s = rsqrtf(var + EPS_);
    }
    __syncthreads();
    float mu = mu_s, rstd = rstd_s;
    float4* row = (float4*)(out + bo*HW_);
    for (int i = threadIdx.x; i < HW_/4; i += 256) {
        float4 v = row[i];
        v.x = fmaxf((v.x - mu)*rstd, 0.f);
        v.y = fmaxf((v.y - mu)*rstd, 0.f);
        v.z = fmaxf((v.z - mu)*rstd, 0.f);
        v.w = fmaxf((v.w - mu)*rstd, 0.f);
        row[i] = v;
    }
}

// ---------------- launch ----------------
extern "C" void kernel_launch(void* const* d_in, const int* in_sizes, int n_in,
                              void* d_out, int out_size) {
    (void)in_sizes; (void)n_in; (void)out_size;
    const float* x     = (const float*)d_in[0];
    const float* dw_w  = (const float*)d_in[1];
    const float* dw_b  = (const float*)d_in[2];
    const float* bn_g  = (const float*)d_in[3];
    const float* bn_b  = (const float*)d_in[4];
    const float* bn_m  = (const float*)d_in[5];
    const float* bn_v  = (const float*)d_in[6];
    const float* pw_w  = (const float*)d_in[7];
    const float* pw_b  = (const float*)d_in[8];
    const float* dcn_w = (const float*)d_in[9];
    // d_in[10] = dcn_b: exactly cancelled by the instance norm -> unused.
    float* out = (float*)d_out;

    cudaFuncSetAttribute(k_main, cudaFuncAttributeMaxDynamicSharedMemorySize, SMEM_BYTES);

    k_transpose<<<dim3((W_/32)*(C_/32), H_, B_), dim3(32, 8)>>>(x);
    k_wprep<<<((J_/2)*O_ + 255)/256, 256>>>(dcn_w);
    k_offsets<<<(B_*HW_)/32, 256>>>(dw_w, dw_b, bn_g, bn_b, bn_m, bn_v, pw_w, pw_b);
    k_main<<<NP_/PXB, 256, SMEM_BYTES>>>(out);
    k_inorm<<<B_*O_, 256>>>(out);
}